// round 11
// baseline (speedup 1.0000x reference)
#include <cuda_runtime.h>
#include <cstdint>

// Problem constants (fixed by reference setup)
#define BB 32
#define NN 128
#define DD 64
#define LN_EPS 1e-5f
#define SLOPE 0.01f

#define IG 4            // i-rows per block
#define THREADS 128
#define ESTRIDE 65      // padded row stride in shared (bank-conflict-free)

__device__ __forceinline__ float warp_sum(float v) {
#pragma unroll
    for (int o = 16; o; o >>= 1) v += __shfl_xor_sync(0xffffffffu, v, o);
    return v;
}
__device__ __forceinline__ float warp_max(float v) {
#pragma unroll
    for (int o = 16; o; o >>= 1) v = fmaxf(v, __shfl_xor_sync(0xffffffffu, v, o));
    return v;
}

__global__ void __launch_bounds__(THREADS)
att_fused_kernel(const float* __restrict__ emb,
                 const float* __restrict__ gam,
                 const float* __restrict__ bet,
                 const float* __restrict__ aw,    // [3*D]: wq | wk | wv
                 const float* __restrict__ ab,    // [1]
                 float* __restrict__ out_alpha,   // [B,N,N]
                 float* __restrict__ out_value)   // [B,N,N,D]
{
    __shared__ float  sh_e[NN * ESTRIDE];   // e[b, j, d] at [j*65 + d]
    __shared__ float4 sh_cf[DD];            // {g*wv, g*wk, g*wq, 0}
    __shared__ float  sh_const[6];          // SGV,SGK,SGQ,SBV,SBK,SBQ
    __shared__ float  sh_q[IG];
    __shared__ float  sh_sc[IG][NN];
    __shared__ float  red_m[IG][4];
    __shared__ float  red_s[IG][4];

    const int tid  = threadIdx.x;
    const int lane = tid & 31;
    const int warp = tid >> 5;

    const int b  = blockIdx.x >> 5;          // 32 i-groups per batch
    const int i0 = (blockIdx.x & 31) * IG;

    const float bias = __ldg(ab);

    // ---- load e[b,:,:] into padded shared ----
    const float* eb = emb + (size_t)b * NN * DD;
    for (int idx = tid; idx < NN * DD; idx += THREADS) {
        sh_e[(idx >> 6) * ESTRIDE + (idx & 63)] = eb[idx];
    }
    // ---- packed per-d coefficients ----
    if (tid < DD) {
        float g = gam[tid];
        sh_cf[tid] = make_float4(g * aw[128 + tid],  // g*wv
                                 g * aw[64 + tid],   // g*wk
                                 g * aw[tid],        // g*wq
                                 0.f);
    }
    // ---- 6 global scalars (warp 0) ----
    if (warp == 0) {
        int d0 = lane * 2, d1 = d0 + 1;
        float g0 = gam[d0], g1 = gam[d1];
        float b0 = bet[d0], b1 = bet[d1];
        float wq0 = aw[d0],       wq1 = aw[d1];
        float wk0 = aw[64 + d0],  wk1 = aw[64 + d1];
        float wv0 = aw[128 + d0], wv1 = aw[128 + d1];
        float sgv = warp_sum(g0 * wv0 + g1 * wv1);
        float sgk = warp_sum(g0 * wk0 + g1 * wk1);
        float sgq = warp_sum(g0 * wq0 + g1 * wq1);
        float sbv = warp_sum(b0 * wv0 + b1 * wv1);
        float sbk = warp_sum(b0 * wk0 + b1 * wk1);
        float sbq = warp_sum(b0 * wq0 + b1 * wq1);
        if (lane == 0) {
            sh_const[0] = sgv; sh_const[1] = sgk; sh_const[2] = sgq;
            sh_const[3] = sbv; sh_const[4] = sbk; sh_const[5] = sbq;
        }
    }
    __syncthreads();

    // ---- Phase B: stream value stores (DRAM-bound, start early) ----
    // warp w handles (ig,j) pairs; 64 contiguous floats per pair.
    for (int w = warp; w < IG * NN; w += 4) {
        int ig = w >> 7;
        int j  = w & 127;
        const float* ei = &sh_e[(i0 + ig) * ESTRIDE];
        const float* ej = &sh_e[j * ESTRIDE];
        float* dst = out_value +
            ((((size_t)(b * NN + i0 + ig)) * NN + j) << 6);
        dst[lane]      = ei[lane]      * ej[lane];
        dst[lane + 32] = ei[lane + 32] * ej[lane + 32];
    }

    // ---- Phase A: per-thread stats (thread t owns column j = t) ----
    {
        const int j = tid;
        float s1v[IG], s2v[IG], svv[IG];
#pragma unroll
        for (int ig = 0; ig < IG; ig++) { s1v[ig] = 0.f; s2v[ig] = 0.f; svv[ig] = 0.f; }
        float t1 = 0.f, t2 = 0.f, tk = 0.f, tq = 0.f;

        const float* erow = &sh_e[j * ESTRIDE];
#pragma unroll 8
        for (int d = 0; d < DD; d++) {
            float ej = erow[d];
            float4 cf = sh_cf[d];
            t1 += ej;
            t2 += ej * ej;
            tk += ej * cf.y;
            tq += ej * cf.z;
#pragma unroll
            for (int ig = 0; ig < IG; ig++) {
                float ei = sh_e[(i0 + ig) * ESTRIDE + d];
                float p = ei * ej;
                s1v[ig] += p;
                s2v[ig] += p * p;
                svv[ig] += p * cf.x;
            }
        }

        const float SGV = sh_const[0], SGK = sh_const[1], SGQ = sh_const[2];
        const float SBV = sh_const[3], SBK = sh_const[4], SBQ = sh_const[5];
        const float inv = 1.0f / 64.0f;

        // row-j layernorm stats drive BOTH k_j and q_j
        float muk  = t1 * inv;
        float vark = fmaxf(t2 * inv - muk * muk, 0.f);
        float rsk  = rsqrtf(vark + LN_EPS);
        float k_t  = rsk * (tk - muk * SGK) + SBK;
        float q_t  = rsk * (tq - muk * SGQ) + SBQ;

        int rel = j - i0;
        if (rel >= 0 && rel < IG) sh_q[rel] = q_t;

        float vsc[IG];
#pragma unroll
        for (int ig = 0; ig < IG; ig++) {
            float mu  = s1v[ig] * inv;
            float var = fmaxf(s2v[ig] * inv - mu * mu, 0.f);
            float rs  = rsqrtf(var + LN_EPS);
            vsc[ig] = rs * (svv[ig] - mu * SGV) + SBV;
        }
        __syncthreads();   // sh_q ready

#pragma unroll
        for (int ig = 0; ig < IG; ig++) {
            float s = sh_q[ig] + k_t + vsc[ig] + bias;
            sh_sc[ig][j] = (s >= 0.f) ? s : SLOPE * s;
        }
    }
    __syncthreads();

    // ---- softmax over j for each of the IG rows, all at once ----
    {
        float x[IG], m[IG];
#pragma unroll
        for (int ig = 0; ig < IG; ig++) {
            x[ig] = sh_sc[ig][tid];
            m[ig] = warp_max(x[ig]);
        }
        if (lane == 0) {
#pragma unroll
            for (int ig = 0; ig < IG; ig++) red_m[ig][warp] = m[ig];
        }
        __syncthreads();
        float ex[IG], s[IG];
#pragma unroll
        for (int ig = 0; ig < IG; ig++) {
            float mm = fmaxf(fmaxf(red_m[ig][0], red_m[ig][1]),
                             fmaxf(red_m[ig][2], red_m[ig][3]));
            ex[ig] = __expf(x[ig] - mm);
            s[ig]  = warp_sum(ex[ig]);
        }
        if (lane == 0) {
#pragma unroll
            for (int ig = 0; ig < IG; ig++) red_s[ig][warp] = s[ig];
        }
        __syncthreads();
#pragma unroll
        for (int ig = 0; ig < IG; ig++) {
            float tot = red_s[ig][0] + red_s[ig][1] + red_s[ig][2] + red_s[ig][3];
            out_alpha[((size_t)(b * NN + i0 + ig)) * NN + tid] = ex[ig] / tot;
        }
    }
}

extern "C" void kernel_launch(void* const* d_in, const int* in_sizes, int n_in,
                              void* d_out, int out_size)
{
    const float* emb = (const float*)d_in[0];
    const float* gam = (const float*)d_in[1];
    const float* bet = (const float*)d_in[2];
    const float* aw  = (const float*)d_in[3];
    const float* ab  = (const float*)d_in[4];

    float* out    = (float*)d_out;
    float* alphas = out;                                   // B*N*N
    float* value  = out + (size_t)BB * NN * NN;            // B*N*N*D

    dim3 grid(BB * (NN / IG));   // 1024 blocks
    att_fused_kernel<<<grid, THREADS>>>(emb, gam, bet, aw, ab, alphas, value);
}

// round 12
// speedup vs baseline: 1.0077x; 1.0077x over previous
#include <cuda_runtime.h>
#include <cstdint>

// Problem constants (fixed by reference setup)
#define BB 32
#define NN 128
#define DD 64
#define LN_EPS 1e-5f
#define SLOPE 0.01f

#define IG 4            // i-rows per block
#define THREADS 128
#define ESTRIDE 65      // padded row stride in shared (bank-conflict-free)

__device__ __forceinline__ float warp_sum(float v) {
#pragma unroll
    for (int o = 16; o; o >>= 1) v += __shfl_xor_sync(0xffffffffu, v, o);
    return v;
}
__device__ __forceinline__ float warp_max(float v) {
#pragma unroll
    for (int o = 16; o; o >>= 1) v = fmaxf(v, __shfl_xor_sync(0xffffffffu, v, o));
    return v;
}

__global__ void __launch_bounds__(THREADS)
att_fused_kernel(const float* __restrict__ emb,
                 const float* __restrict__ gam,
                 const float* __restrict__ bet,
                 const float* __restrict__ aw,    // [3*D]: wq | wk | wv
                 const float* __restrict__ ab,    // [1]
                 float* __restrict__ out_alpha,   // [B,N,N]
                 float* __restrict__ out_value)   // [B,N,N,D]
{
    __shared__ float  sh_e[NN * ESTRIDE];   // e[b, j, d] at [j*65 + d]
    __shared__ float4 sh_cf[DD];            // {g*wv, g*wk, g*wq, 0}
    __shared__ float  sh_const[6];          // SGV,SGK,SGQ,SBV,SBK,SBQ
    __shared__ float  sh_q[IG];
    __shared__ float  sh_sc[IG][NN];
    __shared__ float  red_m[IG][4];
    __shared__ float  red_s[IG][4];

    const int tid  = threadIdx.x;
    const int lane = tid & 31;
    const int warp = tid >> 5;

    const int b  = blockIdx.x >> 5;          // 32 i-groups per batch
    const int i0 = (blockIdx.x & 31) * IG;

    const float bias = __ldg(ab);

    // ---- load e[b,:,:] into padded shared ----
    const float* eb = emb + (size_t)b * NN * DD;
    for (int idx = tid; idx < NN * DD; idx += THREADS) {
        sh_e[(idx >> 6) * ESTRIDE + (idx & 63)] = eb[idx];
    }
    // ---- packed per-d coefficients ----
    if (tid < DD) {
        float g = gam[tid];
        sh_cf[tid] = make_float4(g * aw[128 + tid],  // g*wv
                                 g * aw[64 + tid],   // g*wk
                                 g * aw[tid],        // g*wq
                                 0.f);
    }
    // ---- 6 global scalars (warp 0) ----
    if (warp == 0) {
        int d0 = lane * 2, d1 = d0 + 1;
        float g0 = gam[d0], g1 = gam[d1];
        float b0 = bet[d0], b1 = bet[d1];
        float wq0 = aw[d0],       wq1 = aw[d1];
        float wk0 = aw[64 + d0],  wk1 = aw[64 + d1];
        float wv0 = aw[128 + d0], wv1 = aw[128 + d1];
        float sgv = warp_sum(g0 * wv0 + g1 * wv1);
        float sgk = warp_sum(g0 * wk0 + g1 * wk1);
        float sgq = warp_sum(g0 * wq0 + g1 * wq1);
        float sbv = warp_sum(b0 * wv0 + b1 * wv1);
        float sbk = warp_sum(b0 * wk0 + b1 * wk1);
        float sbq = warp_sum(b0 * wq0 + b1 * wq1);
        if (lane == 0) {
            sh_const[0] = sgv; sh_const[1] = sgk; sh_const[2] = sgq;
            sh_const[3] = sbv; sh_const[4] = sbk; sh_const[5] = sbq;
        }
    }
    __syncthreads();

    // ---- Phase B: stream value stores (DRAM-bound, start early) ----
    // warp w handles (ig,j) pairs; 64 contiguous floats per pair.
    for (int w = warp; w < IG * NN; w += 4) {
        int ig = w >> 7;
        int j  = w & 127;
        const float* ei = &sh_e[(i0 + ig) * ESTRIDE];
        const float* ej = &sh_e[j * ESTRIDE];
        float* dst = out_value +
            ((((size_t)(b * NN + i0 + ig)) * NN + j) << 6);
        dst[lane]      = ei[lane]      * ej[lane];
        dst[lane + 32] = ei[lane + 32] * ej[lane + 32];
    }

    // ---- Phase A: per-thread stats (thread t owns column j = t) ----
    {
        const int j = tid;
        float s1v[IG], s2v[IG], svv[IG];
#pragma unroll
        for (int ig = 0; ig < IG; ig++) { s1v[ig] = 0.f; s2v[ig] = 0.f; svv[ig] = 0.f; }
        float t1 = 0.f, t2 = 0.f, tk = 0.f, tq = 0.f;

        const float* erow = &sh_e[j * ESTRIDE];
#pragma unroll 8
        for (int d = 0; d < DD; d++) {
            float ej = erow[d];
            float4 cf = sh_cf[d];
            t1 += ej;
            t2 += ej * ej;
            tk += ej * cf.y;
            tq += ej * cf.z;
#pragma unroll
            for (int ig = 0; ig < IG; ig++) {
                float ei = sh_e[(i0 + ig) * ESTRIDE + d];
                float p = ei * ej;
                s1v[ig] += p;
                s2v[ig] += p * p;
                svv[ig] += p * cf.x;
            }
        }

        const float SGV = sh_const[0], SGK = sh_const[1], SGQ = sh_const[2];
        const float SBV = sh_const[3], SBK = sh_const[4], SBQ = sh_const[5];
        const float inv = 1.0f / 64.0f;

        // row-j layernorm stats drive BOTH k_j and q_j
        float muk  = t1 * inv;
        float vark = fmaxf(t2 * inv - muk * muk, 0.f);
        float rsk  = rsqrtf(vark + LN_EPS);
        float k_t  = rsk * (tk - muk * SGK) + SBK;
        float q_t  = rsk * (tq - muk * SGQ) + SBQ;

        int rel = j - i0;
        if (rel >= 0 && rel < IG) sh_q[rel] = q_t;

        float vsc[IG];
#pragma unroll
        for (int ig = 0; ig < IG; ig++) {
            float mu  = s1v[ig] * inv;
            float var = fmaxf(s2v[ig] * inv - mu * mu, 0.f);
            float rs  = rsqrtf(var + LN_EPS);
            vsc[ig] = rs * (svv[ig] - mu * SGV) + SBV;
        }
        __syncthreads();   // sh_q ready

#pragma unroll
        for (int ig = 0; ig < IG; ig++) {
            float s = sh_q[ig] + k_t + vsc[ig] + bias;
            sh_sc[ig][j] = (s >= 0.f) ? s : SLOPE * s;
        }
    }
    __syncthreads();

    // ---- softmax over j for each of the IG rows, all at once ----
    {
        float x[IG], m[IG];
#pragma unroll
        for (int ig = 0; ig < IG; ig++) {
            x[ig] = sh_sc[ig][tid];
            m[ig] = warp_max(x[ig]);
        }
        if (lane == 0) {
#pragma unroll
            for (int ig = 0; ig < IG; ig++) red_m[ig][warp] = m[ig];
        }
        __syncthreads();
        float ex[IG], s[IG];
#pragma unroll
        for (int ig = 0; ig < IG; ig++) {
            float mm = fmaxf(fmaxf(red_m[ig][0], red_m[ig][1]),
                             fmaxf(red_m[ig][2], red_m[ig][3]));
            ex[ig] = __expf(x[ig] - mm);
            s[ig]  = warp_sum(ex[ig]);
        }
        if (lane == 0) {
#pragma unroll
            for (int ig = 0; ig < IG; ig++) red_s[ig][warp] = s[ig];
        }
        __syncthreads();
#pragma unroll
        for (int ig = 0; ig < IG; ig++) {
            float tot = red_s[ig][0] + red_s[ig][1] + red_s[ig][2] + red_s[ig][3];
            out_alpha[((size_t)(b * NN + i0 + ig)) * NN + tid] = ex[ig] / tot;
        }
    }
}

extern "C" void kernel_launch(void* const* d_in, const int* in_sizes, int n_in,
                              void* d_out, int out_size)
{
    const float* emb = (const float*)d_in[0];
    const float* gam = (const float*)d_in[1];
    const float* bet = (const float*)d_in[2];
    const float* aw  = (const float*)d_in[3];
    const float* ab  = (const float*)d_in[4];

    float* out    = (float*)d_out;
    float* alphas = out;                                   // B*N*N
    float* value  = out + (size_t)BB * NN * NN;            // B*N*N*D

    dim3 grid(BB * (NN / IG));   // 1024 blocks
    att_fused_kernel<<<grid, THREADS>>>(emb, gam, bet, aw, ab, alphas, value);
}